// round 16
// baseline (speedup 1.0000x reference)
#include <cuda_runtime.h>
#include <cuda_fp16.h>

// ---------------------------------------------------------------------------
// R16: HMMA ConvLSTM, fp16, NB=8, DOUBLE-BUFFERED h/Bx, ONE __syncthreads()
// per step. (R15 design; fixes the R14/R15 bug: shared-space u32 addresses
// were dereferenced as generic pointers. All C-level ld/st now use generic
// smc + offset; shared-space sb + offset is used ONLY inside ldmatrix asm.)
// Step t: mma reads buf[t&1]; cell+scatter write buf[(t+1)&1]; barrier.
// B im2col eliminated: h rows [n][32ch] pitch 80B; tap fragments via
// per-lane-addressed ldmatrix with row shift n+(dy*4+dx); invalid -> zero row.
// Warp (half,T,nhl): A-rows [32T,+32) x n-cols [64*half+32*nhl,+32).
// A row perm: R = 32T + 8g + q <-> oc = g*32 + (8T+q): LSTM fully in-lane.
// Activations: tanh.approx.f32 (sigmoid = 0.5 + 0.5*tanh(v/2)).
// ---------------------------------------------------------------------------

typedef unsigned int u32;
typedef unsigned short u16;

#define NTHR 512
#define NB   8

#define AHI_OFF  0           // 128 x 640B = 81920 (alias: z1/z2 after loop)
#define H0_OFF   81920       // 130 rows x 80B = 10400 (row 128 = zeros)
#define H1_OFF   92320       // 10400
#define BX0_OFF  102720      // 128 x 80B = 10240
#define BX1_OFF  112960      // 10240
#define XS_OFF   123200      // 12*8*48 u16 = 9216
#define HF_OFF   132416      // 8*32 f32 = 1024
#define HFIN_OFF 133440      // [512][8] f32 = 16384
#define SMEM_TOT 149824

static __device__ __forceinline__ u32 sw640(u32 b) { return b ^ ((b >> 3) & 0x70); }

static __device__ __forceinline__ u32 smem_u32(const void* p) {
    u32 a;
    asm("{ .reg .u64 t; cvta.to.shared.u64 t, %1; cvt.u32.u64 %0, t; }" : "=r"(a) : "l"(p));
    return a;
}
static __device__ __forceinline__ float tanh_a(float v) {
    float r;
    asm("tanh.approx.f32 %0, %1;" : "=f"(r) : "f"(v));
    return r;
}
static __device__ __forceinline__ float sig_a(float v) {
    return fmaf(tanh_a(0.5f * v), 0.5f, 0.5f);
}
static __device__ __forceinline__ float sigf(float v) {
    return __fdividef(1.0f, 1.0f + __expf(-v));
}
static __device__ __forceinline__ void ldsm4(u32& r0, u32& r1, u32& r2, u32& r3, u32 a) {
    asm volatile("ldmatrix.sync.aligned.m8n8.x4.shared.b16 {%0,%1,%2,%3}, [%4];"
        : "=r"(r0), "=r"(r1), "=r"(r2), "=r"(r3) : "r"(a));
}
static __device__ __forceinline__ void mma16816(float* d, u32 a0, u32 a1, u32 a2, u32 a3,
                                                u32 b0, u32 b1) {
    asm volatile("mma.sync.aligned.m16n8k16.row.col.f32.f16.f16.f32 "
        "{%0,%1,%2,%3}, {%4,%5,%6,%7}, {%8,%9}, {%0,%1,%2,%3};"
        : "+f"(d[0]), "+f"(d[1]), "+f"(d[2]), "+f"(d[3])
        : "r"(a0), "r"(a1), "r"(a2), "r"(a3), "r"(b0), "r"(b1));
}

extern __shared__ char smc[];

__global__ __launch_bounds__(NTHR, 1)
void wq_hmma9_kernel(const float* __restrict__ x,      const float* __restrict__ hour,
                     const float* __restrict__ conv_w, const float* __restrict__ conv_b,
                     const float* __restrict__ he_w1,  const float* __restrict__ he_b1,
                     const float* __restrict__ he_w2,  const float* __restrict__ he_b2,
                     const float* __restrict__ d_w1,   const float* __restrict__ d_b1,
                     const float* __restrict__ d_w2,   const float* __restrict__ d_b2,
                     const float* __restrict__ d_w3,   const float* __restrict__ d_b3,
                     float* __restrict__ out, int B)
{
    const int tid  = threadIdx.x;
    const int w    = tid >> 5, lane = tid & 31;
    const int half = w >> 3;
    const int wh   = w & 7;
    const int T    = wh >> 1, nhl = wh & 1;
    const int q    = lane >> 2, j = lane & 3;
    const int b0   = blockIdx.x * NB;
    const int tid_h = tid & 255;
    const u32 sb   = smem_u32(smc);
    u16* xs = (u16*)(smc + XS_OFF);

    // ---------------- prologue ----------------
    {   // zero H0,H1,BX0,BX1: contiguous 41280 B = 10320 u32
        u32* bz = (u32*)(smc + H0_OFF);
        for (int e = tid; e < 10320; e += NTHR) bz[e] = 0u;
    }
    for (int e = tid; e < 12 * NB * 48; e += NTHR) {       // 4608
        int t = e / 384, rm = e - t * 384;
        int bb = rm / 48, qq = rm - bb * 48;
        int gb = b0 + bb; if (gb >= B) gb = B - 1;
        xs[e] = __half_as_ushort(__float2half(x[(size_t)gb * 576 + t * 48 + qq]));
    }
    for (int e = tid; e < 128 * 320; e += NTHR) {          // A build: 80/thread
        int R = e / 320, k = e - R * 320;
        int g = (R >> 3) & 3, TT = R >> 5, qq = R & 7;
        int oc = g * 32 + TT * 8 + qq;
        float wv = 0.0f;
        if (k < 288)      wv = conv_w[oc * 315 + (3 + (k & 31)) * 9 + (k >> 5)];
        else if (k < 315) { int m = k - 288; wv = conv_w[oc * 315 + (m % 3) * 9 + (m / 3)]; }
        *(u16*)(smc + AHI_OFF + sw640((u32)(R * 640 + k * 2))) =
            __half_as_ushort(__float2half(wv));
    }
    __syncthreads();

    // Bx scatter for t=0 into BX0
    if (tid < NB * 48) {
        int bb = tid / 48, m = tid - bb * 48;
        int xc = m >> 4, sy = (m >> 2) & 3, sx = m & 3;
        u16 hv = xs[bb * 48 + m];
        #pragma unroll
        for (int dy = 0; dy < 3; dy++) {
            int ny = sy + 1 - dy; if (ny < 0 || ny > 3) continue;
            #pragma unroll
            for (int dx = 0; dx < 3; dx++) {
                int nx = sx + 1 - dx; if (nx < 0 || nx > 3) continue;
                int kl = (dy * 3 + dx) * 3 + xc;
                int n2 = bb * 16 + ny * 4 + nx;
                *(u16*)(smc + BX0_OFF + n2 * 80 + kl * 2) = hv;
            }
        }
    }

    // ---- per-lane A addresses (swizzled pitch 640; shared-space for ldsm) ----
    const u32 araw0 = (u32)((32 * T + (lane & 7) + ((lane >> 3) & 1) * 8) * 640
                            + ((lane >> 4) & 1) * 16);
    const u32 araw1 = araw0 + 16 * 640;

    // ---- per-lane B row relative byte offsets (pitch 80, no swizzle) ----
    const int seg  = (lane >> 3) & 1;
    const int nl1  = half * 64 + 32 * nhl + (lane & 7) + ((lane >> 4) & 1) * 8;
    const int nl2  = nl1 + 16;
    const int rel1 = nl1 * 80 + seg * 16;
    const int rel2 = nl2 * 80 + seg * 16;
    const int relz = 128 * 80 + seg * 16;

    u32 vm1 = 0, vm2 = 0;
    {
        int py1 = (nl1 >> 2) & 3, px1 = nl1 & 3;
        int py2 = (nl2 >> 2) & 3, px2 = nl2 & 3;
        #pragma unroll
        for (int tap = 0; tap < 9; tap++) {
            int dy = tap / 3 - 1, dx = tap % 3 - 1;
            if ((u32)(py1 + dy) < 4u && (u32)(px1 + dx) < 4u) vm1 |= 1u << tap;
            if ((u32)(py2 + dy) < 4u && (u32)(px2 + dx) < 4u) vm2 |= 1u << tap;
        }
    }

    const int ch = 8 * T + q;
    const float bI = conv_b[ch], bF = conv_b[32 + ch];
    const float bO = conv_b[64 + ch], bG = conv_b[96 + ch];

    float cst[8];
    #pragma unroll
    for (int i = 0; i < 8; i++) cst[i] = 0.0f;

    float* hfin = (float*)(smc + HFIN_OFF);

    __syncthreads();

    // ---------------------- 12-step recurrence ----------------------
    #pragma unroll 1
    for (int t = 0; t < 12; ++t) {
        // byte offsets (generic stores use smc + ..., ldsm uses sb + ...)
        const int hcur_off = (t & 1) ? H1_OFF : H0_OFF;
        const int hnxt_off = (t & 1) ? H0_OFF : H1_OFF;
        const int xcur_off = (t & 1) ? BX1_OFF : BX0_OFF;
        const int xnxt_off = (t & 1) ? BX0_OFF : BX1_OFF;

        float accA[4][4], accB[4][4];
        #pragma unroll
        for (int nf = 0; nf < 4; nf++) {
            accA[nf][0] = bI; accA[nf][1] = bI; accA[nf][2] = bF; accA[nf][3] = bF;
            accB[nf][0] = bO; accB[nf][1] = bO; accB[nf][2] = bG; accB[nf][3] = bG;
        }

        // 9 h-taps + 1 x-tap, 2 k-halves each
        #pragma unroll
        for (int tap = 0; tap < 10; ++tap) {
            u32 bA, bB;   // shared-space addresses for ldsm ONLY
            if (tap < 9) {
                const int doff = ((tap / 3 - 1) * 4 + (tap % 3 - 1)) * 80;
                bA = sb + (u32)(hcur_off + (((vm1 >> tap) & 1) ? rel1 + doff : relz));
                bB = sb + (u32)(hcur_off + (((vm2 >> tap) & 1) ? rel2 + doff : relz));
            } else {
                bA = sb + (u32)(xcur_off + rel1);
                bB = sb + (u32)(xcur_off + rel2);
            }
            #pragma unroll
            for (int kh = 0; kh < 2; ++kh) {
                const u32 so = (u32)(tap * 64 + kh * 32);
                u32 a0,a1,a2,a3, a4,a5,a6,a7, p0,p1,p2,p3, p4,p5,p6,p7;
                ldsm4(a0,a1,a2,a3, sb + AHI_OFF + sw640(araw0 + so));
                ldsm4(a4,a5,a6,a7, sb + AHI_OFF + sw640(araw1 + so));
                ldsm4(p0,p1,p2,p3, bA + (u32)(kh * 32));
                ldsm4(p4,p5,p6,p7, bB + (u32)(kh * 32));
                mma16816(accA[0], a0,a1,a2,a3, p0,p1);
                mma16816(accA[1], a0,a1,a2,a3, p2,p3);
                mma16816(accA[2], a0,a1,a2,a3, p4,p5);
                mma16816(accA[3], a0,a1,a2,a3, p6,p7);
                mma16816(accB[0], a4,a5,a6,a7, p0,p1);
                mma16816(accB[1], a4,a5,a6,a7, p2,p3);
                mma16816(accB[2], a4,a5,a6,a7, p4,p5);
                mma16816(accB[3], a4,a5,a6,a7, p6,p7);
            }
        }

        // ---- LSTM cell (in-lane) -> h(t+1) into hnxt (or hfin at t=11) ----
        #pragma unroll
        for (int nf = 0; nf < 4; nf++) {
            #pragma unroll
            for (int cc = 0; cc < 2; cc++) {
                float gi = accA[nf][cc],     gf = accA[nf][2 + cc];
                float go = accB[nf][cc],     gg = accB[nf][2 + cc];
                const int ci = nf * 2 + cc;
                float c = sig_a(gf) * cst[ci] + sig_a(gi) * tanh_a(gg);
                cst[ci] = c;
                float h = sig_a(go) * tanh_a(c);

                const int n = half * 64 + nhl * 32 + nf * 8 + 2 * j + cc;
                if (t < 11) {
                    u32 myh = (u32)__half_as_ushort(__float2half(h));
                    u32 oth = __shfl_down_sync(0xFFFFFFFFu, myh, 4);
                    if ((q & 1) == 0)      // ch even: pack (ch, ch+1); generic ptr
                        *(u32*)(smc + hnxt_off + n * 80 + ch * 2) = myh | (oth << 16);
                } else {
                    hfin[(ch * 16 + (n & 15)) * 8 + (n >> 4)] = h;
                }
            }
        }

        if (t < 11) {
            // Bx scatter for t+1 into xnxt (own half's rows only; generic ptr)
            if (tid_h < 192) {
                int bb = half * 4 + tid_h / 48, m = tid_h % 48;
                int xc = m >> 4, sy2 = (m >> 2) & 3, sx2 = m & 3;
                u16 hv = xs[(t + 1) * 384 + bb * 48 + m];
                #pragma unroll
                for (int dy = 0; dy < 3; dy++) {
                    int ny = sy2 + 1 - dy; if (ny < 0 || ny > 3) continue;
                    #pragma unroll
                    for (int dx = 0; dx < 3; dx++) {
                        int nx = sx2 + 1 - dx; if (nx < 0 || nx > 3) continue;
                        int kl = (dy * 3 + dx) * 3 + xc;
                        int nn = bb * 16 + ny * 4 + nx;
                        *(u16*)(smc + xnxt_off + nn * 80 + kl * 2) = hv;
                    }
                }
            }
        }
        __syncthreads();   // single barrier per step: h(t+1)/Bx(t+1) ready
    }

    // ------------------------------ decoder ------------------------------
    float* hf_s = (float*)(smc + HF_OFF);                 // [8][32]
    float* z1   = (float*)(smc + AHI_OFF);                // [256][8] (A dead)
    float* z2   = (float*)(smc + AHI_OFF + 8192);         // [128][8]
    const int db = tid >> 6, dt = tid & 63;
    const int gb = b0 + db;
    const int gld = (gb < B) ? gb : (B - 1);

    if (dt < 32) {
        float hv = hour[gld];
        float a = he_b2[dt];
        #pragma unroll
        for (int k2 = 0; k2 < 16; ++k2) {
            float tt = fmaxf(hv * he_w1[k2] + he_b1[k2], 0.0f);
            a += tt * he_w2[k2 * 32 + dt];
        }
        hf_s[db * 32 + dt] = a;
    }
    __syncthreads();

    // L1: 544 -> 256, 4 outputs/thread
    {
        const int j0 = dt * 4;
        float a0 = d_b1[j0], a1 = d_b1[j0 + 1], a2 = d_b1[j0 + 2], a3 = d_b1[j0 + 3];
        #pragma unroll 4
        for (int i = 0; i < 512; ++i) {
            float zi = hfin[i * 8 + db];
            float4 w4 = *(const float4*)(d_w1 + i * 256 + j0);
            a0 += zi * w4.x; a1 += zi * w4.y; a2 += zi * w4.z; a3 += zi * w4.w;
        }
        #pragma unroll 4
        for (int i = 0; i < 32; ++i) {
            float zi = hf_s[db * 32 + i];
            float4 w4 = *(const float4*)(d_w1 + (512 + i) * 256 + j0);
            a0 += zi * w4.x; a1 += zi * w4.y; a2 += zi * w4.z; a3 += zi * w4.w;
        }
        z1[(j0 + 0) * 8 + db] = fmaxf(a0, 0.0f);
        z1[(j0 + 1) * 8 + db] = fmaxf(a1, 0.0f);
        z1[(j0 + 2) * 8 + db] = fmaxf(a2, 0.0f);
        z1[(j0 + 3) * 8 + db] = fmaxf(a3, 0.0f);
    }
    __syncthreads();

    // L2: 256 -> 128, 2 outputs/thread
    {
        const int j0 = dt * 2;
        float a0 = d_b2[j0], a1 = d_b2[j0 + 1];
        #pragma unroll 4
        for (int i = 0; i < 256; ++i) {
            float zi = z1[i * 8 + db];
            float2 w2 = *(const float2*)(d_w2 + i * 128 + j0);
            a0 += zi * w2.x; a1 += zi * w2.y;
        }
        z2[(j0 + 0) * 8 + db] = fmaxf(a0, 0.0f);
        z2[(j0 + 1) * 8 + db] = fmaxf(a1, 0.0f);
    }
    __syncthreads();

    // L3: 128 -> 30 + sigmoid (precise)
    if (dt < 30 && gb < B) {
        float a = d_b3[dt];
        #pragma unroll 4
        for (int i = 0; i < 128; ++i)
            a += z2[i * 8 + db] * d_w3[i * 30 + dt];
        out[(size_t)gb * 30 + dt] = sigf(a);
    }
}

extern "C" void kernel_launch(void* const* d_in, const int* in_sizes, int n_in,
                              void* d_out, int out_size)
{
    const float* x      = (const float*)d_in[0];
    const float* hour   = (const float*)d_in[1];
    const float* conv_w = (const float*)d_in[2];
    const float* conv_b = (const float*)d_in[3];
    const float* he_w1  = (const float*)d_in[4];
    const float* he_b1  = (const float*)d_in[5];
    const float* he_w2  = (const float*)d_in[6];
    const float* he_b2  = (const float*)d_in[7];
    const float* d_w1   = (const float*)d_in[8];
    const float* d_b1   = (const float*)d_in[9];
    const float* d_w2   = (const float*)d_in[10];
    const float* d_b2   = (const float*)d_in[11];
    const float* d_w3   = (const float*)d_in[12];
    const float* d_b3   = (const float*)d_in[13];

    const int B    = in_sizes[0] / 576;
    const int grid = (B + NB - 1) / NB;

    cudaFuncSetAttribute(wq_hmma9_kernel,
                         cudaFuncAttributeMaxDynamicSharedMemorySize, SMEM_TOT);

    wq_hmma9_kernel<<<grid, NTHR, SMEM_TOT>>>(x, hour, conv_w, conv_b,
                                              he_w1, he_b1, he_w2, he_b2,
                                              d_w1, d_b1, d_w2, d_b2, d_w3, d_b3,
                                              (float*)d_out, B);
}

// round 17
// speedup vs baseline: 1.0601x; 1.0601x over previous
#include <cuda_runtime.h>
#include <cuda_fp16.h>

// ---------------------------------------------------------------------------
// R17: HMMA ConvLSTM, fp16, NB=8 = R16 double-buffer (1 barrier/step, per-half
// named barrier) + R13 cross-half stagger. (R14 structure, pointer bug fixed:
// generic ld/st use smc + offset; shared-space sb + offset ONLY in ldmatrix.)
// Step t: mma reads buf[t&1]; cell+scatter write buf[(t+1)&1]; barh(1+half).
// Halves own disjoint n-rows; stagger (bar 3) offsets half 1 by one mma phase.
// B im2col eliminated: h rows [n][32ch] pitch 80B; tap fragments via
// per-lane-addressed ldmatrix with row shift n+(dy*4+dx); invalid -> zero row.
// Warp (half,T,nhl): A-rows [32T,+32) x n-cols [64*half+32*nhl,+32).
// A row perm: R = 32T + 8g + q <-> oc = g*32 + (8T+q): LSTM fully in-lane.
// Activations: tanh.approx.f32 (sigmoid = 0.5 + 0.5*tanh(v/2)).
// ---------------------------------------------------------------------------

typedef unsigned int u32;
typedef unsigned short u16;

#define NTHR 512
#define NB   8

#define AHI_OFF  0           // 128 x 640B = 81920 (alias: z1/z2 after loop)
#define H0_OFF   81920       // 130 rows x 80B = 10400 (row 128 = zeros)
#define H1_OFF   92320       // 10400
#define BX0_OFF  102720      // 128 x 80B = 10240
#define BX1_OFF  112960      // 10240
#define XS_OFF   123200      // 12*8*48 u16 = 9216
#define HF_OFF   132416      // 8*32 f32 = 1024
#define HFIN_OFF 133440      // [512][8] f32 = 16384
#define SMEM_TOT 149824

static __device__ __forceinline__ u32 sw640(u32 b) { return b ^ ((b >> 3) & 0x70); }

static __device__ __forceinline__ u32 smem_u32(const void* p) {
    u32 a;
    asm("{ .reg .u64 t; cvta.to.shared.u64 t, %1; cvt.u32.u64 %0, t; }" : "=r"(a) : "l"(p));
    return a;
}
static __device__ __forceinline__ float tanh_a(float v) {
    float r;
    asm("tanh.approx.f32 %0, %1;" : "=f"(r) : "f"(v));
    return r;
}
static __device__ __forceinline__ float sig_a(float v) {
    return fmaf(tanh_a(0.5f * v), 0.5f, 0.5f);
}
static __device__ __forceinline__ float sigf(float v) {
    return __fdividef(1.0f, 1.0f + __expf(-v));
}
static __device__ __forceinline__ void ldsm4(u32& r0, u32& r1, u32& r2, u32& r3, u32 a) {
    asm volatile("ldmatrix.sync.aligned.m8n8.x4.shared.b16 {%0,%1,%2,%3}, [%4];"
        : "=r"(r0), "=r"(r1), "=r"(r2), "=r"(r3) : "r"(a));
}
static __device__ __forceinline__ void mma16816(float* d, u32 a0, u32 a1, u32 a2, u32 a3,
                                                u32 b0, u32 b1) {
    asm volatile("mma.sync.aligned.m16n8k16.row.col.f32.f16.f16.f32 "
        "{%0,%1,%2,%3}, {%4,%5,%6,%7}, {%8,%9}, {%0,%1,%2,%3};"
        : "+f"(d[0]), "+f"(d[1]), "+f"(d[2]), "+f"(d[3])
        : "r"(a0), "r"(a1), "r"(a2), "r"(a3), "r"(b0), "r"(b1));
}
static __device__ __forceinline__ void barh(int id) {
    asm volatile("bar.sync %0, 256;" :: "r"(id) : "memory");
}

extern __shared__ char smc[];

__global__ __launch_bounds__(NTHR, 1)
void wq_hmma10_kernel(const float* __restrict__ x,      const float* __restrict__ hour,
                      const float* __restrict__ conv_w, const float* __restrict__ conv_b,
                      const float* __restrict__ he_w1,  const float* __restrict__ he_b1,
                      const float* __restrict__ he_w2,  const float* __restrict__ he_b2,
                      const float* __restrict__ d_w1,   const float* __restrict__ d_b1,
                      const float* __restrict__ d_w2,   const float* __restrict__ d_b2,
                      const float* __restrict__ d_w3,   const float* __restrict__ d_b3,
                      float* __restrict__ out, int B)
{
    const int tid  = threadIdx.x;
    const int w    = tid >> 5, lane = tid & 31;
    const int half = w >> 3;
    const int wh   = w & 7;
    const int T    = wh >> 1, nhl = wh & 1;
    const int q    = lane >> 2, j = lane & 3;
    const int b0   = blockIdx.x * NB;
    const int tid_h = tid & 255;
    const u32 sb   = smem_u32(smc);
    u16* xs = (u16*)(smc + XS_OFF);

    // ---------------- prologue ----------------
    {   // zero H0,H1,BX0,BX1: contiguous 41280 B = 10320 u32
        u32* bz = (u32*)(smc + H0_OFF);
        for (int e = tid; e < 10320; e += NTHR) bz[e] = 0u;
    }
    for (int e = tid; e < 12 * NB * 48; e += NTHR) {       // 4608
        int t = e / 384, rm = e - t * 384;
        int bb = rm / 48, qq = rm - bb * 48;
        int gb = b0 + bb; if (gb >= B) gb = B - 1;
        xs[e] = __half_as_ushort(__float2half(x[(size_t)gb * 576 + t * 48 + qq]));
    }
    for (int e = tid; e < 128 * 320; e += NTHR) {          // A build: 80/thread
        int R = e / 320, k = e - R * 320;
        int g = (R >> 3) & 3, TT = R >> 5, qq = R & 7;
        int oc = g * 32 + TT * 8 + qq;
        float wv = 0.0f;
        if (k < 288)      wv = conv_w[oc * 315 + (3 + (k & 31)) * 9 + (k >> 5)];
        else if (k < 315) { int m = k - 288; wv = conv_w[oc * 315 + (m % 3) * 9 + (m / 3)]; }
        *(u16*)(smc + AHI_OFF + sw640((u32)(R * 640 + k * 2))) =
            __half_as_ushort(__float2half(wv));
    }
    __syncthreads();

    // Bx scatter for t=0 into BX0
    if (tid < NB * 48) {
        int bb = tid / 48, m = tid - bb * 48;
        int xc = m >> 4, sy = (m >> 2) & 3, sx = m & 3;
        u16 hv = xs[bb * 48 + m];
        #pragma unroll
        for (int dy = 0; dy < 3; dy++) {
            int ny = sy + 1 - dy; if (ny < 0 || ny > 3) continue;
            #pragma unroll
            for (int dx = 0; dx < 3; dx++) {
                int nx = sx + 1 - dx; if (nx < 0 || nx > 3) continue;
                int kl = (dy * 3 + dx) * 3 + xc;
                int n2 = bb * 16 + ny * 4 + nx;
                *(u16*)(smc + BX0_OFF + n2 * 80 + kl * 2) = hv;
            }
        }
    }

    // ---- per-lane A addresses (swizzled pitch 640; shared-space for ldsm) ----
    const u32 araw0 = (u32)((32 * T + (lane & 7) + ((lane >> 3) & 1) * 8) * 640
                            + ((lane >> 4) & 1) * 16);
    const u32 araw1 = araw0 + 16 * 640;

    // ---- per-lane B row relative byte offsets (pitch 80, no swizzle) ----
    const int seg  = (lane >> 3) & 1;
    const int nl1  = half * 64 + 32 * nhl + (lane & 7) + ((lane >> 4) & 1) * 8;
    const int nl2  = nl1 + 16;
    const int rel1 = nl1 * 80 + seg * 16;
    const int rel2 = nl2 * 80 + seg * 16;
    const int relz = 128 * 80 + seg * 16;

    u32 vm1 = 0, vm2 = 0;
    {
        int py1 = (nl1 >> 2) & 3, px1 = nl1 & 3;
        int py2 = (nl2 >> 2) & 3, px2 = nl2 & 3;
        #pragma unroll
        for (int tap = 0; tap < 9; tap++) {
            int dy = tap / 3 - 1, dx = tap % 3 - 1;
            if ((u32)(py1 + dy) < 4u && (u32)(px1 + dx) < 4u) vm1 |= 1u << tap;
            if ((u32)(py2 + dy) < 4u && (u32)(px2 + dx) < 4u) vm2 |= 1u << tap;
        }
    }

    const int ch = 8 * T + q;
    const float bI = conv_b[ch], bF = conv_b[32 + ch];
    const float bO = conv_b[64 + ch], bG = conv_b[96 + ch];

    float cst[8];
    #pragma unroll
    for (int i = 0; i < 8; i++) cst[i] = 0.0f;

    float* hfin = (float*)(smc + HFIN_OFF);

    __syncthreads();

    // ---- one-time stagger: half 1 waits until half 0 finished t=0 mma ----
    if (half == 1)
        asm volatile("bar.sync 3, 512;" ::: "memory");

    const int mybar = 1 + half;

    // ---------------------- 12-step recurrence (per-half) ----------------------
    #pragma unroll 1
    for (int t = 0; t < 12; ++t) {
        const int hcur_off = (t & 1) ? H1_OFF : H0_OFF;
        const int hnxt_off = (t & 1) ? H0_OFF : H1_OFF;
        const int xcur_off = (t & 1) ? BX1_OFF : BX0_OFF;
        const int xnxt_off = (t & 1) ? BX0_OFF : BX1_OFF;

        float accA[4][4], accB[4][4];
        #pragma unroll
        for (int nf = 0; nf < 4; nf++) {
            accA[nf][0] = bI; accA[nf][1] = bI; accA[nf][2] = bF; accA[nf][3] = bF;
            accB[nf][0] = bO; accB[nf][1] = bO; accB[nf][2] = bG; accB[nf][3] = bG;
        }

        // 9 h-taps + 1 x-tap, 2 k-halves each
        #pragma unroll
        for (int tap = 0; tap < 10; ++tap) {
            u32 bA, bB;   // shared-space addresses for ldsm ONLY
            if (tap < 9) {
                const int doff = ((tap / 3 - 1) * 4 + (tap % 3 - 1)) * 80;
                bA = sb + (u32)(hcur_off + (((vm1 >> tap) & 1) ? rel1 + doff : relz));
                bB = sb + (u32)(hcur_off + (((vm2 >> tap) & 1) ? rel2 + doff : relz));
            } else {
                bA = sb + (u32)(xcur_off + rel1);
                bB = sb + (u32)(xcur_off + rel2);
            }
            #pragma unroll
            for (int kh = 0; kh < 2; ++kh) {
                const u32 so = (u32)(tap * 64 + kh * 32);
                u32 a0,a1,a2,a3, a4,a5,a6,a7, p0,p1,p2,p3, p4,p5,p6,p7;
                ldsm4(a0,a1,a2,a3, sb + AHI_OFF + sw640(araw0 + so));
                ldsm4(a4,a5,a6,a7, sb + AHI_OFF + sw640(araw1 + so));
                ldsm4(p0,p1,p2,p3, bA + (u32)(kh * 32));
                ldsm4(p4,p5,p6,p7, bB + (u32)(kh * 32));
                mma16816(accA[0], a0,a1,a2,a3, p0,p1);
                mma16816(accA[1], a0,a1,a2,a3, p2,p3);
                mma16816(accA[2], a0,a1,a2,a3, p4,p5);
                mma16816(accA[3], a0,a1,a2,a3, p6,p7);
                mma16816(accB[0], a4,a5,a6,a7, p0,p1);
                mma16816(accB[1], a4,a5,a6,a7, p2,p3);
                mma16816(accB[2], a4,a5,a6,a7, p4,p5);
                mma16816(accB[3], a4,a5,a6,a7, p6,p7);
            }
        }

        // release half 1 after half 0's first mma phase (non-blocking arrive)
        if (t == 0 && half == 0)
            asm volatile("bar.arrive 3, 512;" ::: "memory");

        // ---- LSTM cell (in-lane) -> h(t+1) into hnxt (or hfin at t=11) ----
        #pragma unroll
        for (int nf = 0; nf < 4; nf++) {
            #pragma unroll
            for (int cc = 0; cc < 2; cc++) {
                float gi = accA[nf][cc],     gf = accA[nf][2 + cc];
                float go = accB[nf][cc],     gg = accB[nf][2 + cc];
                const int ci = nf * 2 + cc;
                float c = sig_a(gf) * cst[ci] + sig_a(gi) * tanh_a(gg);
                cst[ci] = c;
                float h = sig_a(go) * tanh_a(c);

                const int n = half * 64 + nhl * 32 + nf * 8 + 2 * j + cc;
                if (t < 11) {
                    u32 myh = (u32)__half_as_ushort(__float2half(h));
                    u32 oth = __shfl_down_sync(0xFFFFFFFFu, myh, 4);
                    if ((q & 1) == 0)      // ch even: pack (ch, ch+1); generic ptr
                        *(u32*)(smc + hnxt_off + n * 80 + ch * 2) = myh | (oth << 16);
                } else {
                    hfin[(ch * 16 + (n & 15)) * 8 + (n >> 4)] = h;
                }
            }
        }

        if (t < 11) {
            // Bx scatter for t+1 into xnxt (own half's rows only; generic ptr)
            if (tid_h < 192) {
                int bb = half * 4 + tid_h / 48, m = tid_h % 48;
                int xc = m >> 4, sy2 = (m >> 2) & 3, sx2 = m & 3;
                u16 hv = xs[(t + 1) * 384 + bb * 48 + m];
                #pragma unroll
                for (int dy = 0; dy < 3; dy++) {
                    int ny = sy2 + 1 - dy; if (ny < 0 || ny > 3) continue;
                    #pragma unroll
                    for (int dx = 0; dx < 3; dx++) {
                        int nx = sx2 + 1 - dx; if (nx < 0 || nx > 3) continue;
                        int kl = (dy * 3 + dx) * 3 + xc;
                        int nn = bb * 16 + ny * 4 + nx;
                        *(u16*)(smc + xnxt_off + nn * 80 + kl * 2) = hv;
                    }
                }
            }
        }
        barh(mybar);   // single per-half barrier: h(t+1)/Bx(t+1) ready
    }

    __syncthreads();           // both halves done; hfin visible

    // ------------------------------ decoder ------------------------------
    float* hf_s = (float*)(smc + HF_OFF);                 // [8][32]
    float* z1   = (float*)(smc + AHI_OFF);                // [256][8] (A dead)
    float* z2   = (float*)(smc + AHI_OFF + 8192);         // [128][8]
    const int db = tid >> 6, dt = tid & 63;
    const int gb = b0 + db;
    const int gld = (gb < B) ? gb : (B - 1);

    if (dt < 32) {
        float hv = hour[gld];
        float a = he_b2[dt];
        #pragma unroll
        for (int k2 = 0; k2 < 16; ++k2) {
            float tt = fmaxf(hv * he_w1[k2] + he_b1[k2], 0.0f);
            a += tt * he_w2[k2 * 32 + dt];
        }
        hf_s[db * 32 + dt] = a;
    }
    __syncthreads();

    // L1: 544 -> 256, 4 outputs/thread
    {
        const int j0 = dt * 4;
        float a0 = d_b1[j0], a1 = d_b1[j0 + 1], a2 = d_b1[j0 + 2], a3 = d_b1[j0 + 3];
        #pragma unroll 4
        for (int i = 0; i < 512; ++i) {
            float zi = hfin[i * 8 + db];
            float4 w4 = *(const float4*)(d_w1 + i * 256 + j0);
            a0 += zi * w4.x; a1 += zi * w4.y; a2 += zi * w4.z; a3 += zi * w4.w;
        }
        #pragma unroll 4
        for (int i = 0; i < 32; ++i) {
            float zi = hf_s[db * 32 + i];
            float4 w4 = *(const float4*)(d_w1 + (512 + i) * 256 + j0);
            a0 += zi * w4.x; a1 += zi * w4.y; a2 += zi * w4.z; a3 += zi * w4.w;
        }
        z1[(j0 + 0) * 8 + db] = fmaxf(a0, 0.0f);
        z1[(j0 + 1) * 8 + db] = fmaxf(a1, 0.0f);
        z1[(j0 + 2) * 8 + db] = fmaxf(a2, 0.0f);
        z1[(j0 + 3) * 8 + db] = fmaxf(a3, 0.0f);
    }
    __syncthreads();

    // L2: 256 -> 128, 2 outputs/thread
    {
        const int j0 = dt * 2;
        float a0 = d_b2[j0], a1 = d_b2[j0 + 1];
        #pragma unroll 4
        for (int i = 0; i < 256; ++i) {
            float zi = z1[i * 8 + db];
            float2 w2 = *(const float2*)(d_w2 + i * 128 + j0);
            a0 += zi * w2.x; a1 += zi * w2.y;
        }
        z2[(j0 + 0) * 8 + db] = fmaxf(a0, 0.0f);
        z2[(j0 + 1) * 8 + db] = fmaxf(a1, 0.0f);
    }
    __syncthreads();

    // L3: 128 -> 30 + sigmoid (precise)
    if (dt < 30 && gb < B) {
        float a = d_b3[dt];
        #pragma unroll 4
        for (int i = 0; i < 128; ++i)
            a += z2[i * 8 + db] * d_w3[i * 30 + dt];
        out[(size_t)gb * 30 + dt] = sigf(a);
    }
}

extern "C" void kernel_launch(void* const* d_in, const int* in_sizes, int n_in,
                              void* d_out, int out_size)
{
    const float* x      = (const float*)d_in[0];
    const float* hour   = (const float*)d_in[1];
    const float* conv_w = (const float*)d_in[2];
    const float* conv_b = (const float*)d_in[3];
    const float* he_w1  = (const float*)d_in[4];
    const float* he_b1  = (const float*)d_in[5];
    const float* he_w2  = (const float*)d_in[6];
    const float* he_b2  = (const float*)d_in[7];
    const float* d_w1   = (const float*)d_in[8];
    const float* d_b1   = (const float*)d_in[9];
    const float* d_w2   = (const float*)d_in[10];
    const float* d_b2   = (const float*)d_in[11];
    const float* d_w3   = (const float*)d_in[12];
    const float* d_b3   = (const float*)d_in[13];

    const int B    = in_sizes[0] / 576;
    const int grid = (B + NB - 1) / NB;

    cudaFuncSetAttribute(wq_hmma10_kernel,
                         cudaFuncAttributeMaxDynamicSharedMemorySize, SMEM_TOT);

    wq_hmma10_kernel<<<grid, NTHR, SMEM_TOT>>>(x, hour, conv_w, conv_b,
                                               he_w1, he_b1, he_w2, he_b2,
                                               d_w1, d_b1, d_w2, d_b2, d_w3, d_b3,
                                               (float*)d_out, B);
}